// round 10
// baseline (speedup 1.0000x reference)
#include <cuda_runtime.h>

// Problem constants (fixed shapes from reference setup_inputs)
#define ROWS   153600      // N*M*T
#define D      256
#define D4     64          // D/4
#define KCLS   5
#define NB     256         // N
#define MB     2           // M
#define TB     300         // T
#define TOPK   64
#define CC     3           // C
#define VV     25          // V
#define SEL_ELEMS (NB*CC*TOPK*VV*MB)   // 2,457,600
#define EPSF   1e-8f

// ---------------- scratch (device globals; zero at module load) ----------
// Invariant: every kernel_launch call both STARTS and ENDS with
// g_sums/g_counts/g_Sw zeroed (k_topk re-zeroes them after use), so the
// captured graph is replay-safe without a separate init kernel.
__device__ float  g_sums[KCLS*D];
__device__ int    g_counts[KCLS];
__device__ double g_Sb;
__device__ double g_Sw;
__device__ float  g_fs[ROWS];
__device__ int    g_idx[NB*TOPK];

__device__ __forceinline__ void f4add(float4& d, const float4 a) {
    d.x += a.x; d.y += a.y; d.z += a.z; d.w += a.w;
}

// ---------------- kernel 1: per-class sums + counts ----------------
// Warp-per-8-rows (two 4-row groups software-pipelined: all 16 LDG.128 +
// both label int4 loads issued before any accumulation -> 16 loads in
// flight per warp). Full-row warps (lane + lane+32), per-lane REGISTER
// accumulators for the 5 classes (labels warp-uniform -> uniform branch).
// Grid 600 * 8 warps = 4800 warps; 153600/(4800*8) = 4 exact iterations.
__global__ void __launch_bounds__(256, 2) k_segsum(const float4* __restrict__ xT,
                                                   const int* __restrict__ lab) {
    __shared__ float4 s_sums[8][KCLS][D4];   // 40 KB
    __shared__ int    s_cnt[KCLS];
    const int tid  = threadIdx.x;
    const int w    = tid >> 5;
    const int lane = tid & 31;
    if (tid < KCLS) s_cnt[tid] = 0;

    float4 c0a = {0,0,0,0}, c0b = {0,0,0,0};
    float4 c1a = {0,0,0,0}, c1b = {0,0,0,0};
    float4 c2a = {0,0,0,0}, c2b = {0,0,0,0};
    float4 c3a = {0,0,0,0}, c3b = {0,0,0,0};
    float4 c4a = {0,0,0,0}, c4b = {0,0,0,0};
    int cnt0 = 0, cnt1 = 0, cnt2 = 0, cnt3 = 0, cnt4 = 0;

#define ACCUM(l, a, b)                                        \
    if ((l) == 0)      { f4add(c0a, a); f4add(c0b, b); cnt0++; } \
    else if ((l) == 1) { f4add(c1a, a); f4add(c1b, b); cnt1++; } \
    else if ((l) == 2) { f4add(c2a, a); f4add(c2b, b); cnt2++; } \
    else if ((l) == 3) { f4add(c3a, a); f4add(c3b, b); cnt3++; } \
    else               { f4add(c4a, a); f4add(c4b, b); cnt4++; }

    const int gw = blockIdx.x * 8 + w;
    const int nw = gridDim.x * 8;
    for (int r0 = gw * 8; r0 < ROWS; r0 += nw * 8) {
        // ---- issue ALL loads for both 4-row groups up front ----
        const int4 LA = *(const int4*)(lab + r0);
        const int4 LB = *(const int4*)(lab + r0 + 4);
        const size_t base = (size_t)r0 * D4;
        const float4 a0 = xT[base       + lane], b0 = xT[base +  32 + lane];
        const float4 a1 = xT[base +  64 + lane], b1 = xT[base +  96 + lane];
        const float4 a2 = xT[base + 128 + lane], b2 = xT[base + 160 + lane];
        const float4 a3 = xT[base + 192 + lane], b3 = xT[base + 224 + lane];
        const float4 e0 = xT[base + 256 + lane], f0 = xT[base + 288 + lane];
        const float4 e1 = xT[base + 320 + lane], f1 = xT[base + 352 + lane];
        const float4 e2 = xT[base + 384 + lane], f2 = xT[base + 416 + lane];
        const float4 e3 = xT[base + 448 + lane], f3 = xT[base + 480 + lane];
        // ---- accumulate (branchy, but loads already in flight) ----
        ACCUM(LA.x, a0, b0);
        ACCUM(LA.y, a1, b1);
        ACCUM(LA.z, a2, b2);
        ACCUM(LA.w, a3, b3);
        ACCUM(LB.x, e0, f0);
        ACCUM(LB.y, e1, f1);
        ACCUM(LB.z, e2, f2);
        ACCUM(LB.w, e3, f3);
    }
#undef ACCUM

    // flush: per-warp regs -> smem, combine 8 copies, atomics to global
    s_sums[w][0][lane] = c0a;  s_sums[w][0][lane + 32] = c0b;
    s_sums[w][1][lane] = c1a;  s_sums[w][1][lane + 32] = c1b;
    s_sums[w][2][lane] = c2a;  s_sums[w][2][lane + 32] = c2b;
    s_sums[w][3][lane] = c3a;  s_sums[w][3][lane + 32] = c3b;
    s_sums[w][4][lane] = c4a;  s_sums[w][4][lane + 32] = c4b;
    __syncthreads();
    if (lane == 0) {
        atomicAdd(&s_cnt[0], cnt0); atomicAdd(&s_cnt[1], cnt1);
        atomicAdd(&s_cnt[2], cnt2); atomicAdd(&s_cnt[3], cnt3);
        atomicAdd(&s_cnt[4], cnt4);
    }
    __syncthreads();
    for (int i = tid; i < KCLS*D4; i += blockDim.x) {
        const int k = i / D4, c = i % D4;
        float4 acc = {0,0,0,0};
        #pragma unroll
        for (int cp = 0; cp < 8; cp++) f4add(acc, s_sums[cp][k][c]);
        float* gp = &g_sums[k*D + c*4];
        atomicAdd(gp+0, acc.x); atomicAdd(gp+1, acc.y);
        atomicAdd(gp+2, acc.z); atomicAdd(gp+3, acc.w);
    }
    if (tid < KCLS && s_cnt[tid] != 0) atomicAdd(&g_counts[tid], s_cnt[tid]);
}

// ---------------- kernel 2: [stats prologue] + per-row intra, Sw, scores ----
__device__ __forceinline__ float dist8(const float4 a, const float4 b,
                                       const float4 ma, const float4 mb) {
    float d, v = 0.f;
    d = a.x - ma.x; v += d*d;  d = a.y - ma.y; v += d*d;
    d = a.z - ma.z; v += d*d;  d = a.w - ma.w; v += d*d;
    d = b.x - mb.x; v += d*d;  d = b.y - mb.y; v += d*d;
    d = b.z - mb.z; v += d*d;  d = b.w - mb.w; v += d*d;
    return v;
}

// Warp-per-6-rows: 12 LDG.128 front-batched (48 data regs; ~110 total, no
// spill under the 128-reg cap). ALIGNMENT: r0 = gw*6 is always EVEN but not
// a multiple of 4, so labels are loaded as 3x int2 (8B-aligned) and g_fs is
// stored as 3x float2 (8B-aligned). xT row loads are float4-aligned always
// (base = r0*64 float4s).
// Grid 400 * 8 warps = 3200 warps; 153600/(3200*6) = 8 exact iterations.
__global__ void __launch_bounds__(256, 2) k_intra(const float4* __restrict__ xT,
                                                  const int* __restrict__ lab) {
    __shared__ float s_cm[KCLS*D];     // 5 KB (float4-aligned)
    __shared__ float s_inter[KCLS];
    __shared__ float s_cntf[KCLS];
    __shared__ float s_red[8];
    const int tid  = threadIdx.x;
    const int w    = tid >> 5;
    const int lane = tid & 31;

    // --- stats prologue (every block redundantly; g_sums is L2-resident) ---
    if (tid < KCLS) s_cntf[tid] = (float)g_counts[tid];
    __syncthreads();
    float cmv[KCLS];
    float tot = 0.f;
    #pragma unroll
    for (int k = 0; k < KCLS; k++) {
        const float s = g_sums[k*D + tid];
        tot += s;
        cmv[k] = s / fmaxf(s_cntf[k], 1.f);
        s_cm[k*D + tid] = cmv[k];
    }
    const float ov = tot / (float)ROWS;
    #pragma unroll
    for (int k = 0; k < KCLS; k++) {
        const float dd = cmv[k] - ov;
        float v = dd * dd;
        #pragma unroll
        for (int off = 16; off; off >>= 1) v += __shfl_down_sync(0xffffffffu, v, off);
        if (lane == 0) s_red[w] = v;
        __syncthreads();
        if (tid == 0) {
            float s = 0.f;
            #pragma unroll
            for (int i = 0; i < 8; i++) s += s_red[i];
            s_inter[k] = s;
        }
        __syncthreads();
    }
    if (blockIdx.x == 0 && tid == 0) {
        double sb = 0.0;
        #pragma unroll
        for (int k = 0; k < KCLS; k++) sb += (double)s_cntf[k] * (double)s_inter[k];
        g_Sb = sb;
    }

    // --- main loop: warp-per-6-rows, 12 loads in flight ---
    const float4* cm4 = (const float4*)s_cm;
    const int gw = blockIdx.x * 8 + w;
    const int nw = gridDim.x * 8;
    double sw = 0.0;
    for (int r0 = gw * 6; r0 < ROWS; r0 += nw * 6) {
        // labels as 3x int2 (r0 even -> 8B-aligned)
        const int2 L0 = *(const int2*)(lab + r0);
        const int2 L1 = *(const int2*)(lab + r0 + 2);
        const int2 L2 = *(const int2*)(lab + r0 + 4);
        const size_t base = (size_t)r0 * D4;
        const float4 a0 = xT[base       + lane], b0 = xT[base +  32 + lane];
        const float4 a1 = xT[base +  64 + lane], b1 = xT[base +  96 + lane];
        const float4 a2 = xT[base + 128 + lane], b2 = xT[base + 160 + lane];
        const float4 a3 = xT[base + 192 + lane], b3 = xT[base + 224 + lane];
        const float4 a4 = xT[base + 256 + lane], b4 = xT[base + 288 + lane];
        const float4 a5 = xT[base + 320 + lane], b5 = xT[base + 352 + lane];
        const float4* m0 = &cm4[L0.x * D4];
        const float4* m1 = &cm4[L0.y * D4];
        const float4* m2 = &cm4[L1.x * D4];
        const float4* m3 = &cm4[L1.y * D4];
        const float4* m4 = &cm4[L2.x * D4];
        const float4* m5 = &cm4[L2.y * D4];
        float v0 = dist8(a0, b0, m0[lane], m0[lane + 32]);
        float v1 = dist8(a1, b1, m1[lane], m1[lane + 32]);
        float v2 = dist8(a2, b2, m2[lane], m2[lane + 32]);
        float v3 = dist8(a3, b3, m3[lane], m3[lane + 32]);
        float v4 = dist8(a4, b4, m4[lane], m4[lane + 32]);
        float v5 = dist8(a5, b5, m5[lane], m5[lane + 32]);
        #pragma unroll
        for (int off = 16; off; off >>= 1) {
            v0 += __shfl_down_sync(0xffffffffu, v0, off);
            v1 += __shfl_down_sync(0xffffffffu, v1, off);
            v2 += __shfl_down_sync(0xffffffffu, v2, off);
            v3 += __shfl_down_sync(0xffffffffu, v3, off);
            v4 += __shfl_down_sync(0xffffffffu, v4, off);
            v5 += __shfl_down_sync(0xffffffffu, v5, off);
        }
        if (lane == 0) {
            const float s0 = s_inter[L0.x] / (v0 + EPSF);
            const float s1 = s_inter[L0.y] / (v1 + EPSF);
            const float s2 = s_inter[L1.x] / (v2 + EPSF);
            const float s3 = s_inter[L1.y] / (v3 + EPSF);
            const float s4 = s_inter[L2.x] / (v4 + EPSF);
            const float s5 = s_inter[L2.y] / (v5 + EPSF);
            *(float2*)&g_fs[r0]     = make_float2(s0, s1);
            *(float2*)&g_fs[r0 + 2] = make_float2(s2, s3);
            *(float2*)&g_fs[r0 + 4] = make_float2(s4, s5);
            sw += (double)v0; sw += (double)v1;
            sw += (double)v2; sw += (double)v3;
            sw += (double)v4; sw += (double)v5;
        }
    }
    if (lane == 0) atomicAdd(&g_Sw, sw);
}

// ---------------- kernel 3: top-64 per sample + loss + re-zero scratch ----
// One block per n. Exact jax.lax.top_k semantics: rank by (value desc, index
// asc), select rank<TOPK, emit in ascending index order (== sorted indices).
// Rank loop vectorized: s_v read as float4 (75 warp-broadcast LDS.128).
// Block 0 also writes the loss and re-zeroes accumulators for the next replay.
__global__ void k_topk(float* __restrict__ out, int sel_off) {
    __shared__ float s_v[TB];          // 300 floats, 16B-aligned
    __shared__ int s_warpcnt[10];
    const int n = blockIdx.x;
    const int t = threadIdx.x;
    const int w = t >> 5, lane = t & 31;
    if (t < TB) {
        const float a = g_fs[(n*2 + 0)*TB + t];
        const float b = g_fs[(n*2 + 1)*TB + t];
        s_v[t] = 0.5f * (a + b);
    }
    if (n == 0) {
        // loss + scratch re-zero (g_Sw read happens before its zeroing: same thread)
        if (t == 0 && sel_off >= 1) {
            out[0] = (float)(g_Sw / (g_Sb + 1e-8));
            g_Sw = 0.0;
        }
        for (int i = t; i < KCLS*D; i += blockDim.x) g_sums[i] = 0.f;
        if (t < KCLS) g_counts[t] = 0;
    }
    __syncthreads();
    int sel = 0;
    if (t < TB) {
        const float v = s_v[t];
        const float4* sv4 = (const float4*)s_v;
        int rank = 0;
        #pragma unroll 5
        for (int j4 = 0; j4 < TB/4; j4++) {
            const float4 q = sv4[j4];
            const int jb = j4 * 4;
            rank += (q.x > v) || (q.x == v && jb     < t);
            rank += (q.y > v) || (q.y == v && jb + 1 < t);
            rank += (q.z > v) || (q.z == v && jb + 2 < t);
            rank += (q.w > v) || (q.w == v && jb + 3 < t);
        }
        sel = (rank < TOPK);
    }
    const unsigned bal = __ballot_sync(0xffffffffu, sel);
    if (lane == 0) s_warpcnt[w] = __popc(bal);
    __syncthreads();
    if (sel) {
        int base = 0;
        for (int i = 0; i < w; i++) base += s_warpcnt[i];
        const int pos = base + __popc(bal & ((1u << lane) - 1u));
        g_idx[n*TOPK + pos] = t;
    }
}

// ---------------- kernel 4: flat gather, 4 elements per thread ----------
// Each block owns a 1024-element tile of float2 output elements; thread tid
// handles tile+tid, +256, +512, +768 (coalesced within each group, 4
// independent load chains in flight). Scalar stores (dst 4B-aligned only).
__global__ void __launch_bounds__(256) k_gather(const float2* __restrict__ x,
                                                float* __restrict__ out,
                                                int sel_off) {
    const int TOT2 = NB * CC * TOPK * VV;    // 1,228,800 float2 elems
    const int base = blockIdx.x * 1024 + threadIdx.x;
    int   idx[4];
    float2 val[4];
    #pragma unroll
    for (int k = 0; k < 4; k++) {
        const int i = base + k * 256;
        idx[k] = i;
        if (i < TOT2) {
            const int v   = i % VV;
            const int r1  = i / VV;
            const int j   = r1 & (TOPK - 1);
            const int r2  = r1 >> 6;
            const int c   = r2 % CC;
            const int n   = r2 / CC;
            const int t   = __ldg(&g_idx[n*TOPK + j]);
            val[k] = __ldg(&x[((size_t)(n*CC + c) * TB + t) * VV + v]);
        }
    }
    #pragma unroll
    for (int k = 0; k < 4; k++) {
        if (idx[k] < TOT2) {
            float* op = out + sel_off + 2*(size_t)idx[k];
            op[0] = val[k].x;
            op[1] = val[k].y;
        }
    }
}

extern "C" void kernel_launch(void* const* d_in, const int* in_sizes, int n_in,
                              void* d_out, int out_size) {
    const float2* x   = (const float2*)d_in[0];   // x [256,3,300,25,2]
    const float4* xT  = (const float4*)d_in[1];   // x_T [153600, 256]
    const int*    lab = (const int*)d_in[2];      // labels [153600] int32
    float* out = (float*)d_out;

    const int sel_off = out_size - SEL_ELEMS;     // loss scalar(s) precede x_select

    k_segsum<<<600, 256>>>(xT, lab);
    k_intra<<<400, 256>>>(xT, lab);
    k_topk<<<NB, 320>>>(out, sel_off);
    const int TOT2 = NB * CC * TOPK * VV;
    k_gather<<<(TOT2 + 1023) / 1024, 256>>>(x, out, sel_off);
}

// round 11
// speedup vs baseline: 1.1269x; 1.1269x over previous
#include <cuda_runtime.h>

// Problem constants (fixed shapes from reference setup_inputs)
#define ROWS   153600      // N*M*T
#define D      256
#define D4     64          // D/4
#define KCLS   5
#define NB     256         // N
#define MB     2           // M
#define TB     300         // T
#define TOPK   64
#define CC     3           // C
#define VV     25          // V
#define SEL_ELEMS (NB*CC*TOPK*VV*MB)   // 2,457,600
#define EPSF   1e-8f

// ---------------- scratch (device globals; zero at module load) ----------
// Invariant: every kernel_launch call both STARTS and ENDS with
// g_sums/g_counts/g_Sw zeroed (k_topk re-zeroes them after use), so the
// captured graph is replay-safe without a separate init kernel.
__device__ float  g_sums[KCLS*D];
__device__ int    g_counts[KCLS];
__device__ double g_Sb;
__device__ double g_Sw;
__device__ float  g_fs[ROWS];
__device__ int    g_idx[NB*TOPK];

__device__ __forceinline__ void f4add(float4& d, const float4 a) {
    d.x += a.x; d.y += a.y; d.z += a.z; d.w += a.w;
}

// ---------------- kernel 1: per-class sums + counts ----------------
// Warp-per-8-rows (two 4-row groups software-pipelined: all 16 LDG.128 +
// both label int4 loads issued before any accumulation -> 16 loads in
// flight per warp). Full-row warps (lane + lane+32), per-lane REGISTER
// accumulators for the 5 classes (labels warp-uniform -> uniform branch).
// Grid 600 * 8 warps = 4800 warps; 153600/(4800*8) = 4 exact iterations.
__global__ void __launch_bounds__(256, 2) k_segsum(const float4* __restrict__ xT,
                                                   const int* __restrict__ lab) {
    __shared__ float4 s_sums[8][KCLS][D4];   // 40 KB
    __shared__ int    s_cnt[KCLS];
    const int tid  = threadIdx.x;
    const int w    = tid >> 5;
    const int lane = tid & 31;
    if (tid < KCLS) s_cnt[tid] = 0;

    float4 c0a = {0,0,0,0}, c0b = {0,0,0,0};
    float4 c1a = {0,0,0,0}, c1b = {0,0,0,0};
    float4 c2a = {0,0,0,0}, c2b = {0,0,0,0};
    float4 c3a = {0,0,0,0}, c3b = {0,0,0,0};
    float4 c4a = {0,0,0,0}, c4b = {0,0,0,0};
    int cnt0 = 0, cnt1 = 0, cnt2 = 0, cnt3 = 0, cnt4 = 0;

#define ACCUM(l, a, b)                                        \
    if ((l) == 0)      { f4add(c0a, a); f4add(c0b, b); cnt0++; } \
    else if ((l) == 1) { f4add(c1a, a); f4add(c1b, b); cnt1++; } \
    else if ((l) == 2) { f4add(c2a, a); f4add(c2b, b); cnt2++; } \
    else if ((l) == 3) { f4add(c3a, a); f4add(c3b, b); cnt3++; } \
    else               { f4add(c4a, a); f4add(c4b, b); cnt4++; }

    const int gw = blockIdx.x * 8 + w;
    const int nw = gridDim.x * 8;
    for (int r0 = gw * 8; r0 < ROWS; r0 += nw * 8) {
        // ---- issue ALL loads for both 4-row groups up front ----
        const int4 LA = *(const int4*)(lab + r0);
        const int4 LB = *(const int4*)(lab + r0 + 4);
        const size_t base = (size_t)r0 * D4;
        const float4 a0 = xT[base       + lane], b0 = xT[base +  32 + lane];
        const float4 a1 = xT[base +  64 + lane], b1 = xT[base +  96 + lane];
        const float4 a2 = xT[base + 128 + lane], b2 = xT[base + 160 + lane];
        const float4 a3 = xT[base + 192 + lane], b3 = xT[base + 224 + lane];
        const float4 e0 = xT[base + 256 + lane], f0 = xT[base + 288 + lane];
        const float4 e1 = xT[base + 320 + lane], f1 = xT[base + 352 + lane];
        const float4 e2 = xT[base + 384 + lane], f2 = xT[base + 416 + lane];
        const float4 e3 = xT[base + 448 + lane], f3 = xT[base + 480 + lane];
        // ---- accumulate (branchy, but loads already in flight) ----
        ACCUM(LA.x, a0, b0);
        ACCUM(LA.y, a1, b1);
        ACCUM(LA.z, a2, b2);
        ACCUM(LA.w, a3, b3);
        ACCUM(LB.x, e0, f0);
        ACCUM(LB.y, e1, f1);
        ACCUM(LB.z, e2, f2);
        ACCUM(LB.w, e3, f3);
    }
#undef ACCUM

    // flush: per-warp regs -> smem, combine 8 copies, atomics to global
    s_sums[w][0][lane] = c0a;  s_sums[w][0][lane + 32] = c0b;
    s_sums[w][1][lane] = c1a;  s_sums[w][1][lane + 32] = c1b;
    s_sums[w][2][lane] = c2a;  s_sums[w][2][lane + 32] = c2b;
    s_sums[w][3][lane] = c3a;  s_sums[w][3][lane + 32] = c3b;
    s_sums[w][4][lane] = c4a;  s_sums[w][4][lane + 32] = c4b;
    __syncthreads();
    if (lane == 0) {
        atomicAdd(&s_cnt[0], cnt0); atomicAdd(&s_cnt[1], cnt1);
        atomicAdd(&s_cnt[2], cnt2); atomicAdd(&s_cnt[3], cnt3);
        atomicAdd(&s_cnt[4], cnt4);
    }
    __syncthreads();
    for (int i = tid; i < KCLS*D4; i += blockDim.x) {
        const int k = i / D4, c = i % D4;
        float4 acc = {0,0,0,0};
        #pragma unroll
        for (int cp = 0; cp < 8; cp++) f4add(acc, s_sums[cp][k][c]);
        float* gp = &g_sums[k*D + c*4];
        atomicAdd(gp+0, acc.x); atomicAdd(gp+1, acc.y);
        atomicAdd(gp+2, acc.z); atomicAdd(gp+3, acc.w);
    }
    if (tid < KCLS && s_cnt[tid] != 0) atomicAdd(&g_counts[tid], s_cnt[tid]);
}

// ---------------- kernel 2: [stats prologue] + per-row intra, Sw, scores ----
__device__ __forceinline__ float dist8(const float4 a, const float4 b,
                                       const float4 ma, const float4 mb) {
    float d, v = 0.f;
    d = a.x - ma.x; v += d*d;  d = a.y - ma.y; v += d*d;
    d = a.z - ma.z; v += d*d;  d = a.w - ma.w; v += d*d;
    d = b.x - mb.x; v += d*d;  d = b.y - mb.y; v += d*d;
    d = b.z - mb.z; v += d*d;  d = b.w - mb.w; v += d*d;
    return v;
}

// Warp-per-4-rows, 8 loads in flight, 4 overlapped reduces (R7 proven form).
__global__ void __launch_bounds__(256) k_intra(const float4* __restrict__ xT,
                                               const int* __restrict__ lab) {
    __shared__ float s_cm[KCLS*D];     // 5 KB (float4-aligned)
    __shared__ float s_inter[KCLS];
    __shared__ float s_cntf[KCLS];
    __shared__ float s_red[8];
    const int tid  = threadIdx.x;
    const int w    = tid >> 5;
    const int lane = tid & 31;

    // --- stats prologue (every block redundantly; g_sums is L2-resident) ---
    if (tid < KCLS) s_cntf[tid] = (float)g_counts[tid];
    __syncthreads();
    float cmv[KCLS];
    float tot = 0.f;
    #pragma unroll
    for (int k = 0; k < KCLS; k++) {
        const float s = g_sums[k*D + tid];
        tot += s;
        cmv[k] = s / fmaxf(s_cntf[k], 1.f);
        s_cm[k*D + tid] = cmv[k];
    }
    const float ov = tot / (float)ROWS;
    #pragma unroll
    for (int k = 0; k < KCLS; k++) {
        const float dd = cmv[k] - ov;
        float v = dd * dd;
        #pragma unroll
        for (int off = 16; off; off >>= 1) v += __shfl_down_sync(0xffffffffu, v, off);
        if (lane == 0) s_red[w] = v;
        __syncthreads();
        if (tid == 0) {
            float s = 0.f;
            #pragma unroll
            for (int i = 0; i < 8; i++) s += s_red[i];
            s_inter[k] = s;
        }
        __syncthreads();
    }
    if (blockIdx.x == 0 && tid == 0) {
        double sb = 0.0;
        #pragma unroll
        for (int k = 0; k < KCLS; k++) sb += (double)s_cntf[k] * (double)s_inter[k];
        g_Sb = sb;
    }

    // --- main loop: warp-per-4-rows, 8 loads in flight, 4 overlapped reduces ---
    const float4* cm4 = (const float4*)s_cm;
    const int gw = blockIdx.x * 8 + w;
    const int nw = gridDim.x * 8;
    double sw = 0.0;
    for (int r0 = gw * 4; r0 < ROWS; r0 += nw * 4) {
        const int4 L = *(const int4*)(lab + r0);
        const size_t base = (size_t)r0 * D4;
        const float4 a0 = xT[base       + lane], b0 = xT[base +  32 + lane];
        const float4 a1 = xT[base +  64 + lane], b1 = xT[base +  96 + lane];
        const float4 a2 = xT[base + 128 + lane], b2 = xT[base + 160 + lane];
        const float4 a3 = xT[base + 192 + lane], b3 = xT[base + 224 + lane];
        const float4* m0 = &cm4[L.x * D4];
        const float4* m1 = &cm4[L.y * D4];
        const float4* m2 = &cm4[L.z * D4];
        const float4* m3 = &cm4[L.w * D4];
        float v0 = dist8(a0, b0, m0[lane], m0[lane + 32]);
        float v1 = dist8(a1, b1, m1[lane], m1[lane + 32]);
        float v2 = dist8(a2, b2, m2[lane], m2[lane + 32]);
        float v3 = dist8(a3, b3, m3[lane], m3[lane + 32]);
        #pragma unroll
        for (int off = 16; off; off >>= 1) {
            v0 += __shfl_down_sync(0xffffffffu, v0, off);
            v1 += __shfl_down_sync(0xffffffffu, v1, off);
            v2 += __shfl_down_sync(0xffffffffu, v2, off);
            v3 += __shfl_down_sync(0xffffffffu, v3, off);
        }
        if (lane == 0) {
            const float s0 = s_inter[L.x] / (v0 + EPSF);
            const float s1 = s_inter[L.y] / (v1 + EPSF);
            const float s2 = s_inter[L.z] / (v2 + EPSF);
            const float s3 = s_inter[L.w] / (v3 + EPSF);
            *(float4*)&g_fs[r0] = make_float4(s0, s1, s2, s3);
            sw += (double)v0; sw += (double)v1;
            sw += (double)v2; sw += (double)v3;
        }
    }
    if (lane == 0) atomicAdd(&g_Sw, sw);
}

// ---------------- kernel 3: top-64 per sample + loss + re-zero scratch ----
// One block per n. Exact jax.lax.top_k semantics: rank by (value desc, index
// asc), select rank<TOPK, emit in ascending index order (== sorted indices).
// Rank loop vectorized: s_v read as float4 (75 warp-broadcast LDS.128).
// Block 0 also writes the loss and re-zeroes accumulators for the next replay.
__global__ void k_topk(float* __restrict__ out, int sel_off) {
    __shared__ float s_v[TB];          // 300 floats, 16B-aligned
    __shared__ int s_warpcnt[10];
    const int n = blockIdx.x;
    const int t = threadIdx.x;
    const int w = t >> 5, lane = t & 31;
    if (t < TB) {
        const float a = g_fs[(n*2 + 0)*TB + t];
        const float b = g_fs[(n*2 + 1)*TB + t];
        s_v[t] = 0.5f * (a + b);
    }
    if (n == 0) {
        // loss + scratch re-zero (g_Sw read happens before its zeroing: same thread)
        if (t == 0 && sel_off >= 1) {
            out[0] = (float)(g_Sw / (g_Sb + 1e-8));
            g_Sw = 0.0;
        }
        for (int i = t; i < KCLS*D; i += blockDim.x) g_sums[i] = 0.f;
        if (t < KCLS) g_counts[t] = 0;
    }
    __syncthreads();
    int sel = 0;
    if (t < TB) {
        const float v = s_v[t];
        const float4* sv4 = (const float4*)s_v;
        int rank = 0;
        #pragma unroll 5
        for (int j4 = 0; j4 < TB/4; j4++) {
            const float4 q = sv4[j4];
            const int jb = j4 * 4;
            rank += (q.x > v) || (q.x == v && jb     < t);
            rank += (q.y > v) || (q.y == v && jb + 1 < t);
            rank += (q.z > v) || (q.z == v && jb + 2 < t);
            rank += (q.w > v) || (q.w == v && jb + 3 < t);
        }
        sel = (rank < TOPK);
    }
    const unsigned bal = __ballot_sync(0xffffffffu, sel);
    if (lane == 0) s_warpcnt[w] = __popc(bal);
    __syncthreads();
    if (sel) {
        int base = 0;
        for (int i = 0; i < w; i++) base += s_warpcnt[i];
        const int pos = base + __popc(bal & ((1u << lane) - 1u));
        g_idx[n*TOPK + pos] = t;
    }
}

// ---------------- kernel 4: flat gather, 8 elements per thread ----------
// 128-thread blocks, 1024-element tiles, grid 1200 (same block count as the
// measured-best 4/thread config -> occupancy preserved) but 8 independent
// load chains per thread (2x MLP). Scalar stores (dst 4B-aligned only).
__global__ void __launch_bounds__(128) k_gather(const float2* __restrict__ x,
                                                float* __restrict__ out,
                                                int sel_off) {
    const int TOT2 = NB * CC * TOPK * VV;    // 1,228,800 float2 elems
    const int base = blockIdx.x * 1024 + threadIdx.x;
    int   idx[8];
    float2 val[8];
    #pragma unroll
    for (int k = 0; k < 8; k++) {
        const int i = base + k * 128;
        idx[k] = i;
        if (i < TOT2) {
            const int v   = i % VV;
            const int r1  = i / VV;
            const int j   = r1 & (TOPK - 1);
            const int r2  = r1 >> 6;
            const int c   = r2 % CC;
            const int n   = r2 / CC;
            const int t   = __ldg(&g_idx[n*TOPK + j]);
            val[k] = __ldg(&x[((size_t)(n*CC + c) * TB + t) * VV + v]);
        }
    }
    #pragma unroll
    for (int k = 0; k < 8; k++) {
        if (idx[k] < TOT2) {
            float* op = out + sel_off + 2*(size_t)idx[k];
            op[0] = val[k].x;
            op[1] = val[k].y;
        }
    }
}

extern "C" void kernel_launch(void* const* d_in, const int* in_sizes, int n_in,
                              void* d_out, int out_size) {
    const float2* x   = (const float2*)d_in[0];   // x [256,3,300,25,2]
    const float4* xT  = (const float4*)d_in[1];   // x_T [153600, 256]
    const int*    lab = (const int*)d_in[2];      // labels [153600] int32
    float* out = (float*)d_out;

    const int sel_off = out_size - SEL_ELEMS;     // loss scalar(s) precede x_select

    k_segsum<<<600, 256>>>(xT, lab);
    k_intra<<<600, 256>>>(xT, lab);
    k_topk<<<NB, 320>>>(out, sel_off);
    const int TOT2 = NB * CC * TOPK * VV;
    k_gather<<<(TOT2 + 1023) / 1024, 128>>>(x, out, sel_off);
}

// round 12
// speedup vs baseline: 1.2098x; 1.0735x over previous
#include <cuda_runtime.h>

// Problem constants (fixed shapes from reference setup_inputs)
#define ROWS   153600      // N*M*T
#define D      256
#define D4     64          // D/4
#define KCLS   5
#define NB     256         // N
#define MB     2           // M
#define TB     300         // T
#define TOPK   64
#define CC     3           // C
#define VV     25          // V
#define SEL_ELEMS (NB*CC*TOPK*VV*MB)   // 2,457,600
#define EPSF   1e-8f

// ---------------- scratch (device globals; zero at module load) ----------
// Invariant: every kernel_launch call both STARTS and ENDS with
// g_sums/g_counts/g_Sw zeroed (k_topk re-zeroes them after use), so the
// captured graph is replay-safe without a separate init kernel.
__device__ float  g_sums[KCLS*D];
__device__ int    g_counts[KCLS];
__device__ double g_Sb;
__device__ double g_Sw;
__device__ float  g_fs[ROWS];
__device__ int    g_idx[NB*TOPK];

__device__ __forceinline__ void f4add(float4& d, const float4 a) {
    d.x += a.x; d.y += a.y; d.z += a.z; d.w += a.w;
}

// ---------------- kernel 1: per-class sums + counts ----------------
// Warp-per-8-rows (two 4-row groups software-pipelined: all 16 LDG.128 +
// both label int4 loads issued before any accumulation -> 16 loads in
// flight per warp). Full-row warps (lane + lane+32), per-lane REGISTER
// accumulators for the 5 classes (labels warp-uniform -> uniform branch).
// Grid 296 = exactly one resident wave (2 blocks/SM x 148 SMs) -> no
// straggler wave; grid-stride absorbs the remainder.
__global__ void __launch_bounds__(256, 2) k_segsum(const float4* __restrict__ xT,
                                                   const int* __restrict__ lab) {
    __shared__ float4 s_sums[8][KCLS][D4];   // 40 KB
    __shared__ int    s_cnt[KCLS];
    const int tid  = threadIdx.x;
    const int w    = tid >> 5;
    const int lane = tid & 31;
    if (tid < KCLS) s_cnt[tid] = 0;

    float4 c0a = {0,0,0,0}, c0b = {0,0,0,0};
    float4 c1a = {0,0,0,0}, c1b = {0,0,0,0};
    float4 c2a = {0,0,0,0}, c2b = {0,0,0,0};
    float4 c3a = {0,0,0,0}, c3b = {0,0,0,0};
    float4 c4a = {0,0,0,0}, c4b = {0,0,0,0};
    int cnt0 = 0, cnt1 = 0, cnt2 = 0, cnt3 = 0, cnt4 = 0;

#define ACCUM(l, a, b)                                        \
    if ((l) == 0)      { f4add(c0a, a); f4add(c0b, b); cnt0++; } \
    else if ((l) == 1) { f4add(c1a, a); f4add(c1b, b); cnt1++; } \
    else if ((l) == 2) { f4add(c2a, a); f4add(c2b, b); cnt2++; } \
    else if ((l) == 3) { f4add(c3a, a); f4add(c3b, b); cnt3++; } \
    else               { f4add(c4a, a); f4add(c4b, b); cnt4++; }

    const int gw = blockIdx.x * 8 + w;
    const int nw = gridDim.x * 8;
    for (int r0 = gw * 8; r0 < ROWS; r0 += nw * 8) {
        // ---- issue ALL loads for both 4-row groups up front ----
        const int4 LA = *(const int4*)(lab + r0);
        const int4 LB = *(const int4*)(lab + r0 + 4);
        const size_t base = (size_t)r0 * D4;
        const float4 a0 = xT[base       + lane], b0 = xT[base +  32 + lane];
        const float4 a1 = xT[base +  64 + lane], b1 = xT[base +  96 + lane];
        const float4 a2 = xT[base + 128 + lane], b2 = xT[base + 160 + lane];
        const float4 a3 = xT[base + 192 + lane], b3 = xT[base + 224 + lane];
        const float4 e0 = xT[base + 256 + lane], f0 = xT[base + 288 + lane];
        const float4 e1 = xT[base + 320 + lane], f1 = xT[base + 352 + lane];
        const float4 e2 = xT[base + 384 + lane], f2 = xT[base + 416 + lane];
        const float4 e3 = xT[base + 448 + lane], f3 = xT[base + 480 + lane];
        // ---- accumulate (branchy, but loads already in flight) ----
        ACCUM(LA.x, a0, b0);
        ACCUM(LA.y, a1, b1);
        ACCUM(LA.z, a2, b2);
        ACCUM(LA.w, a3, b3);
        ACCUM(LB.x, e0, f0);
        ACCUM(LB.y, e1, f1);
        ACCUM(LB.z, e2, f2);
        ACCUM(LB.w, e3, f3);
    }
#undef ACCUM

    // flush: per-warp regs -> smem, combine 8 copies, atomics to global
    s_sums[w][0][lane] = c0a;  s_sums[w][0][lane + 32] = c0b;
    s_sums[w][1][lane] = c1a;  s_sums[w][1][lane + 32] = c1b;
    s_sums[w][2][lane] = c2a;  s_sums[w][2][lane + 32] = c2b;
    s_sums[w][3][lane] = c3a;  s_sums[w][3][lane + 32] = c3b;
    s_sums[w][4][lane] = c4a;  s_sums[w][4][lane + 32] = c4b;
    __syncthreads();
    if (lane == 0) {
        atomicAdd(&s_cnt[0], cnt0); atomicAdd(&s_cnt[1], cnt1);
        atomicAdd(&s_cnt[2], cnt2); atomicAdd(&s_cnt[3], cnt3);
        atomicAdd(&s_cnt[4], cnt4);
    }
    __syncthreads();
    for (int i = tid; i < KCLS*D4; i += blockDim.x) {
        const int k = i / D4, c = i % D4;
        float4 acc = {0,0,0,0};
        #pragma unroll
        for (int cp = 0; cp < 8; cp++) f4add(acc, s_sums[cp][k][c]);
        float* gp = &g_sums[k*D + c*4];
        atomicAdd(gp+0, acc.x); atomicAdd(gp+1, acc.y);
        atomicAdd(gp+2, acc.z); atomicAdd(gp+3, acc.w);
    }
    if (tid < KCLS && s_cnt[tid] != 0) atomicAdd(&g_counts[tid], s_cnt[tid]);
}

// ---------------- kernel 2: [stats prologue] + per-row intra, Sw, scores ----
__device__ __forceinline__ float dist8(const float4 a, const float4 b,
                                       const float4 ma, const float4 mb) {
    float d, v = 0.f;
    d = a.x - ma.x; v += d*d;  d = a.y - ma.y; v += d*d;
    d = a.z - ma.z; v += d*d;  d = a.w - ma.w; v += d*d;
    d = b.x - mb.x; v += d*d;  d = b.y - mb.y; v += d*d;
    d = b.z - mb.z; v += d*d;  d = b.w - mb.w; v += d*d;
    return v;
}

// Warp-per-4-rows, 8 loads in flight, 4 overlapped reduces (R7 proven form).
// Grid 592 = exact multiple of plausible residency (4/SM) -> no 8-block tail.
__global__ void __launch_bounds__(256) k_intra(const float4* __restrict__ xT,
                                               const int* __restrict__ lab) {
    __shared__ float s_cm[KCLS*D];     // 5 KB (float4-aligned)
    __shared__ float s_inter[KCLS];
    __shared__ float s_cntf[KCLS];
    __shared__ float s_red[8];
    const int tid  = threadIdx.x;
    const int w    = tid >> 5;
    const int lane = tid & 31;

    // --- stats prologue (every block redundantly; g_sums is L2-resident) ---
    if (tid < KCLS) s_cntf[tid] = (float)g_counts[tid];
    __syncthreads();
    float cmv[KCLS];
    float tot = 0.f;
    #pragma unroll
    for (int k = 0; k < KCLS; k++) {
        const float s = g_sums[k*D + tid];
        tot += s;
        cmv[k] = s / fmaxf(s_cntf[k], 1.f);
        s_cm[k*D + tid] = cmv[k];
    }
    const float ov = tot / (float)ROWS;
    #pragma unroll
    for (int k = 0; k < KCLS; k++) {
        const float dd = cmv[k] - ov;
        float v = dd * dd;
        #pragma unroll
        for (int off = 16; off; off >>= 1) v += __shfl_down_sync(0xffffffffu, v, off);
        if (lane == 0) s_red[w] = v;
        __syncthreads();
        if (tid == 0) {
            float s = 0.f;
            #pragma unroll
            for (int i = 0; i < 8; i++) s += s_red[i];
            s_inter[k] = s;
        }
        __syncthreads();
    }
    if (blockIdx.x == 0 && tid == 0) {
        double sb = 0.0;
        #pragma unroll
        for (int k = 0; k < KCLS; k++) sb += (double)s_cntf[k] * (double)s_inter[k];
        g_Sb = sb;
    }

    // --- main loop: warp-per-4-rows, 8 loads in flight, 4 overlapped reduces ---
    const float4* cm4 = (const float4*)s_cm;
    const int gw = blockIdx.x * 8 + w;
    const int nw = gridDim.x * 8;
    double sw = 0.0;
    for (int r0 = gw * 4; r0 < ROWS; r0 += nw * 4) {
        const int4 L = *(const int4*)(lab + r0);
        const size_t base = (size_t)r0 * D4;
        const float4 a0 = xT[base       + lane], b0 = xT[base +  32 + lane];
        const float4 a1 = xT[base +  64 + lane], b1 = xT[base +  96 + lane];
        const float4 a2 = xT[base + 128 + lane], b2 = xT[base + 160 + lane];
        const float4 a3 = xT[base + 192 + lane], b3 = xT[base + 224 + lane];
        const float4* m0 = &cm4[L.x * D4];
        const float4* m1 = &cm4[L.y * D4];
        const float4* m2 = &cm4[L.z * D4];
        const float4* m3 = &cm4[L.w * D4];
        float v0 = dist8(a0, b0, m0[lane], m0[lane + 32]);
        float v1 = dist8(a1, b1, m1[lane], m1[lane + 32]);
        float v2 = dist8(a2, b2, m2[lane], m2[lane + 32]);
        float v3 = dist8(a3, b3, m3[lane], m3[lane + 32]);
        #pragma unroll
        for (int off = 16; off; off >>= 1) {
            v0 += __shfl_down_sync(0xffffffffu, v0, off);
            v1 += __shfl_down_sync(0xffffffffu, v1, off);
            v2 += __shfl_down_sync(0xffffffffu, v2, off);
            v3 += __shfl_down_sync(0xffffffffu, v3, off);
        }
        if (lane == 0) {
            const float s0 = s_inter[L.x] / (v0 + EPSF);
            const float s1 = s_inter[L.y] / (v1 + EPSF);
            const float s2 = s_inter[L.z] / (v2 + EPSF);
            const float s3 = s_inter[L.w] / (v3 + EPSF);
            *(float4*)&g_fs[r0] = make_float4(s0, s1, s2, s3);
            sw += (double)v0; sw += (double)v1;
            sw += (double)v2; sw += (double)v3;
        }
    }
    if (lane == 0) atomicAdd(&g_Sw, sw);
}

// ---------------- kernel 3: top-64 per sample + loss + re-zero scratch ----
// One block per n. Exact jax.lax.top_k semantics: rank by (value desc, index
// asc), select rank<TOPK, emit in ascending index order (== sorted indices).
// Rank loop vectorized: s_v read as float4 (75 warp-broadcast LDS.128).
// Block 0 also writes the loss and re-zeroes accumulators for the next replay.
__global__ void k_topk(float* __restrict__ out, int sel_off) {
    __shared__ float s_v[TB];          // 300 floats, 16B-aligned
    __shared__ int s_warpcnt[10];
    const int n = blockIdx.x;
    const int t = threadIdx.x;
    const int w = t >> 5, lane = t & 31;
    if (t < TB) {
        const float a = g_fs[(n*2 + 0)*TB + t];
        const float b = g_fs[(n*2 + 1)*TB + t];
        s_v[t] = 0.5f * (a + b);
    }
    if (n == 0) {
        // loss + scratch re-zero (g_Sw read happens before its zeroing: same thread)
        if (t == 0 && sel_off >= 1) {
            out[0] = (float)(g_Sw / (g_Sb + 1e-8));
            g_Sw = 0.0;
        }
        for (int i = t; i < KCLS*D; i += blockDim.x) g_sums[i] = 0.f;
        if (t < KCLS) g_counts[t] = 0;
    }
    __syncthreads();
    int sel = 0;
    if (t < TB) {
        const float v = s_v[t];
        const float4* sv4 = (const float4*)s_v;
        int rank = 0;
        #pragma unroll 5
        for (int j4 = 0; j4 < TB/4; j4++) {
            const float4 q = sv4[j4];
            const int jb = j4 * 4;
            rank += (q.x > v) || (q.x == v && jb     < t);
            rank += (q.y > v) || (q.y == v && jb + 1 < t);
            rank += (q.z > v) || (q.z == v && jb + 2 < t);
            rank += (q.w > v) || (q.w == v && jb + 3 < t);
        }
        sel = (rank < TOPK);
    }
    const unsigned bal = __ballot_sync(0xffffffffu, sel);
    if (lane == 0) s_warpcnt[w] = __popc(bal);
    __syncthreads();
    if (sel) {
        int base = 0;
        for (int i = 0; i < w; i++) base += s_warpcnt[i];
        const int pos = base + __popc(bal & ((1u << lane) - 1u));
        g_idx[n*TOPK + pos] = t;
    }
}

// ---------------- kernel 4: flat gather, 4 elements per thread ----------
// Each block owns a 1024-element tile of float2 output elements; thread tid
// handles tile+tid, +256, +512, +768 (coalesced within each group, 4
// independent load chains in flight). Scalar stores (dst 4B-aligned only).
__global__ void __launch_bounds__(256) k_gather(const float2* __restrict__ x,
                                                float* __restrict__ out,
                                                int sel_off) {
    const int TOT2 = NB * CC * TOPK * VV;    // 1,228,800 float2 elems
    const int base = blockIdx.x * 1024 + threadIdx.x;
    int   idx[4];
    float2 val[4];
    #pragma unroll
    for (int k = 0; k < 4; k++) {
        const int i = base + k * 256;
        idx[k] = i;
        if (i < TOT2) {
            const int v   = i % VV;
            const int r1  = i / VV;
            const int j   = r1 & (TOPK - 1);
            const int r2  = r1 >> 6;
            const int c   = r2 % CC;
            const int n   = r2 / CC;
            const int t   = __ldg(&g_idx[n*TOPK + j]);
            val[k] = __ldg(&x[((size_t)(n*CC + c) * TB + t) * VV + v]);
        }
    }
    #pragma unroll
    for (int k = 0; k < 4; k++) {
        if (idx[k] < TOT2) {
            float* op = out + sel_off + 2*(size_t)idx[k];
            op[0] = val[k].x;
            op[1] = val[k].y;
        }
    }
}

extern "C" void kernel_launch(void* const* d_in, const int* in_sizes, int n_in,
                              void* d_out, int out_size) {
    const float2* x   = (const float2*)d_in[0];   // x [256,3,300,25,2]
    const float4* xT  = (const float4*)d_in[1];   // x_T [153600, 256]
    const int*    lab = (const int*)d_in[2];      // labels [153600] int32
    float* out = (float*)d_out;

    const int sel_off = out_size - SEL_ELEMS;     // loss scalar(s) precede x_select

    k_segsum<<<296, 256>>>(xT, lab);
    k_intra<<<592, 256>>>(xT, lab);
    k_topk<<<NB, 320>>>(out, sel_off);
    const int TOT2 = NB * CC * TOPK * VV;
    k_gather<<<(TOT2 + 1023) / 1024, 256>>>(x, out, sel_off);
}

// round 13
// speedup vs baseline: 1.3314x; 1.1005x over previous
#include <cuda_runtime.h>

// Problem constants (fixed shapes from reference setup_inputs)
#define ROWS   153600      // N*M*T
#define D      256
#define D4     64          // D/4
#define KCLS   5
#define NB     256         // N
#define MB     2           // M
#define TB     300         // T
#define TOPK   64
#define CC     3           // C
#define VV     25          // V
#define SEL_ELEMS (NB*CC*TOPK*VV*MB)   // 2,457,600
#define EPSF   1e-8f

// ---------------- scratch (device globals; zero at module load) ----------
// Invariant: every kernel_launch call both STARTS and ENDS with
// g_sums/g_counts/g_Sw zeroed (k_topk re-zeroes them after use), so the
// captured graph is replay-safe without a separate init kernel.
__device__ float  g_sums[KCLS*D];
__device__ int    g_counts[KCLS];
__device__ double g_Sb;
__device__ double g_Sw;
__device__ float  g_fs[ROWS];
__device__ int    g_idx[NB*TOPK];

__device__ __forceinline__ void f4add(float4& d, const float4 a) {
    d.x += a.x; d.y += a.y; d.z += a.z; d.w += a.w;
}

// ---------------- kernel 1: per-class sums + counts ----------------
// Warp-per-8-rows, FORWARD row order (low->high addresses). Paired with
// k_intra's REVERSE order this ping-pongs the L2: segsum's tail stays hot
// for intra's head, and intra's tail (low addresses) stays hot for the
// NEXT replay's segsum head.
// Grid 296 = exactly one resident wave (2 blocks/SM x 148 SMs).
__global__ void __launch_bounds__(256, 2) k_segsum(const float4* __restrict__ xT,
                                                   const int* __restrict__ lab) {
    __shared__ float4 s_sums[8][KCLS][D4];   // 40 KB
    __shared__ int    s_cnt[KCLS];
    const int tid  = threadIdx.x;
    const int w    = tid >> 5;
    const int lane = tid & 31;
    if (tid < KCLS) s_cnt[tid] = 0;

    float4 c0a = {0,0,0,0}, c0b = {0,0,0,0};
    float4 c1a = {0,0,0,0}, c1b = {0,0,0,0};
    float4 c2a = {0,0,0,0}, c2b = {0,0,0,0};
    float4 c3a = {0,0,0,0}, c3b = {0,0,0,0};
    float4 c4a = {0,0,0,0}, c4b = {0,0,0,0};
    int cnt0 = 0, cnt1 = 0, cnt2 = 0, cnt3 = 0, cnt4 = 0;

#define ACCUM(l, a, b)                                        \
    if ((l) == 0)      { f4add(c0a, a); f4add(c0b, b); cnt0++; } \
    else if ((l) == 1) { f4add(c1a, a); f4add(c1b, b); cnt1++; } \
    else if ((l) == 2) { f4add(c2a, a); f4add(c2b, b); cnt2++; } \
    else if ((l) == 3) { f4add(c3a, a); f4add(c3b, b); cnt3++; } \
    else               { f4add(c4a, a); f4add(c4b, b); cnt4++; }

    const int gw = blockIdx.x * 8 + w;
    const int nw = gridDim.x * 8;
    for (int r0 = gw * 8; r0 < ROWS; r0 += nw * 8) {
        // ---- issue ALL loads for both 4-row groups up front ----
        const int4 LA = *(const int4*)(lab + r0);
        const int4 LB = *(const int4*)(lab + r0 + 4);
        const size_t base = (size_t)r0 * D4;
        const float4 a0 = xT[base       + lane], b0 = xT[base +  32 + lane];
        const float4 a1 = xT[base +  64 + lane], b1 = xT[base +  96 + lane];
        const float4 a2 = xT[base + 128 + lane], b2 = xT[base + 160 + lane];
        const float4 a3 = xT[base + 192 + lane], b3 = xT[base + 224 + lane];
        const float4 e0 = xT[base + 256 + lane], f0 = xT[base + 288 + lane];
        const float4 e1 = xT[base + 320 + lane], f1 = xT[base + 352 + lane];
        const float4 e2 = xT[base + 384 + lane], f2 = xT[base + 416 + lane];
        const float4 e3 = xT[base + 448 + lane], f3 = xT[base + 480 + lane];
        // ---- accumulate (branchy, but loads already in flight) ----
        ACCUM(LA.x, a0, b0);
        ACCUM(LA.y, a1, b1);
        ACCUM(LA.z, a2, b2);
        ACCUM(LA.w, a3, b3);
        ACCUM(LB.x, e0, f0);
        ACCUM(LB.y, e1, f1);
        ACCUM(LB.z, e2, f2);
        ACCUM(LB.w, e3, f3);
    }
#undef ACCUM

    // flush: per-warp regs -> smem, combine 8 copies, atomics to global
    s_sums[w][0][lane] = c0a;  s_sums[w][0][lane + 32] = c0b;
    s_sums[w][1][lane] = c1a;  s_sums[w][1][lane + 32] = c1b;
    s_sums[w][2][lane] = c2a;  s_sums[w][2][lane + 32] = c2b;
    s_sums[w][3][lane] = c3a;  s_sums[w][3][lane + 32] = c3b;
    s_sums[w][4][lane] = c4a;  s_sums[w][4][lane + 32] = c4b;
    __syncthreads();
    if (lane == 0) {
        atomicAdd(&s_cnt[0], cnt0); atomicAdd(&s_cnt[1], cnt1);
        atomicAdd(&s_cnt[2], cnt2); atomicAdd(&s_cnt[3], cnt3);
        atomicAdd(&s_cnt[4], cnt4);
    }
    __syncthreads();
    for (int i = tid; i < KCLS*D4; i += blockDim.x) {
        const int k = i / D4, c = i % D4;
        float4 acc = {0,0,0,0};
        #pragma unroll
        for (int cp = 0; cp < 8; cp++) f4add(acc, s_sums[cp][k][c]);
        float* gp = &g_sums[k*D + c*4];
        atomicAdd(gp+0, acc.x); atomicAdd(gp+1, acc.y);
        atomicAdd(gp+2, acc.z); atomicAdd(gp+3, acc.w);
    }
    if (tid < KCLS && s_cnt[tid] != 0) atomicAdd(&g_counts[tid], s_cnt[tid]);
}

// ---------------- kernel 2: [stats prologue] + per-row intra, Sw, scores ----
__device__ __forceinline__ float dist8(const float4 a, const float4 b,
                                       const float4 ma, const float4 mb) {
    float d, v = 0.f;
    d = a.x - ma.x; v += d*d;  d = a.y - ma.y; v += d*d;
    d = a.z - ma.z; v += d*d;  d = a.w - ma.w; v += d*d;
    d = b.x - mb.x; v += d*d;  d = b.y - mb.y; v += d*d;
    d = b.z - mb.z; v += d*d;  d = b.w - mb.w; v += d*d;
    return v;
}

// Warp-per-4-rows, 8 loads in flight, 4 overlapped reduces. REVERSE global
// row order (tail-first): the tail of xT is what k_segsum read last, so it
// is L2-resident when this kernel starts -> large DRAM-traffic cut.
__global__ void __launch_bounds__(256) k_intra(const float4* __restrict__ xT,
                                               const int* __restrict__ lab) {
    __shared__ float s_cm[KCLS*D];     // 5 KB (float4-aligned)
    __shared__ float s_inter[KCLS];
    __shared__ float s_cntf[KCLS];
    __shared__ float s_red[8];
    const int tid  = threadIdx.x;
    const int w    = tid >> 5;
    const int lane = tid & 31;

    // --- stats prologue (every block redundantly; g_sums is L2-resident) ---
    if (tid < KCLS) s_cntf[tid] = (float)g_counts[tid];
    __syncthreads();
    float cmv[KCLS];
    float tot = 0.f;
    #pragma unroll
    for (int k = 0; k < KCLS; k++) {
        const float s = g_sums[k*D + tid];
        tot += s;
        cmv[k] = s / fmaxf(s_cntf[k], 1.f);
        s_cm[k*D + tid] = cmv[k];
    }
    const float ov = tot / (float)ROWS;
    #pragma unroll
    for (int k = 0; k < KCLS; k++) {
        const float dd = cmv[k] - ov;
        float v = dd * dd;
        #pragma unroll
        for (int off = 16; off; off >>= 1) v += __shfl_down_sync(0xffffffffu, v, off);
        if (lane == 0) s_red[w] = v;
        __syncthreads();
        if (tid == 0) {
            float s = 0.f;
            #pragma unroll
            for (int i = 0; i < 8; i++) s += s_red[i];
            s_inter[k] = s;
        }
        __syncthreads();
    }
    if (blockIdx.x == 0 && tid == 0) {
        double sb = 0.0;
        #pragma unroll
        for (int k = 0; k < KCLS; k++) sb += (double)s_cntf[k] * (double)s_inter[k];
        g_Sb = sb;
    }

    // --- main loop: REVERSED group order (g = G-1-k), tail-first ---
    const float4* cm4 = (const float4*)s_cm;
    const int G  = ROWS / 4;           // 38400 4-row groups
    const int gw = blockIdx.x * 8 + w;
    const int nw = gridDim.x * 8;
    double sw = 0.0;
    for (int k = gw; k < G; k += nw) {
        const int r0 = (G - 1 - k) * 4;
        const int4 L = *(const int4*)(lab + r0);
        const size_t base = (size_t)r0 * D4;
        const float4 a0 = xT[base       + lane], b0 = xT[base +  32 + lane];
        const float4 a1 = xT[base +  64 + lane], b1 = xT[base +  96 + lane];
        const float4 a2 = xT[base + 128 + lane], b2 = xT[base + 160 + lane];
        const float4 a3 = xT[base + 192 + lane], b3 = xT[base + 224 + lane];
        const float4* m0 = &cm4[L.x * D4];
        const float4* m1 = &cm4[L.y * D4];
        const float4* m2 = &cm4[L.z * D4];
        const float4* m3 = &cm4[L.w * D4];
        float v0 = dist8(a0, b0, m0[lane], m0[lane + 32]);
        float v1 = dist8(a1, b1, m1[lane], m1[lane + 32]);
        float v2 = dist8(a2, b2, m2[lane], m2[lane + 32]);
        float v3 = dist8(a3, b3, m3[lane], m3[lane + 32]);
        #pragma unroll
        for (int off = 16; off; off >>= 1) {
            v0 += __shfl_down_sync(0xffffffffu, v0, off);
            v1 += __shfl_down_sync(0xffffffffu, v1, off);
            v2 += __shfl_down_sync(0xffffffffu, v2, off);
            v3 += __shfl_down_sync(0xffffffffu, v3, off);
        }
        if (lane == 0) {
            const float s0 = s_inter[L.x] / (v0 + EPSF);
            const float s1 = s_inter[L.y] / (v1 + EPSF);
            const float s2 = s_inter[L.z] / (v2 + EPSF);
            const float s3 = s_inter[L.w] / (v3 + EPSF);
            *(float4*)&g_fs[r0] = make_float4(s0, s1, s2, s3);
            sw += (double)v0; sw += (double)v1;
            sw += (double)v2; sw += (double)v3;
        }
    }
    if (lane == 0) atomicAdd(&g_Sw, sw);
}

// ---------------- kernel 3: top-64 per sample + loss + re-zero scratch ----
// One block per n. Exact jax.lax.top_k semantics: rank by (value desc, index
// asc), select rank<TOPK, emit in ascending index order (== sorted indices).
// Rank loop vectorized: s_v read as float4 (75 warp-broadcast LDS.128).
// Block 0 also writes the loss and re-zeroes accumulators for the next replay.
__global__ void k_topk(float* __restrict__ out, int sel_off) {
    __shared__ float s_v[TB];          // 300 floats, 16B-aligned
    __shared__ int s_warpcnt[10];
    const int n = blockIdx.x;
    const int t = threadIdx.x;
    const int w = t >> 5, lane = t & 31;
    if (t < TB) {
        const float a = g_fs[(n*2 + 0)*TB + t];
        const float b = g_fs[(n*2 + 1)*TB + t];
        s_v[t] = 0.5f * (a + b);
    }
    if (n == 0) {
        // loss + scratch re-zero (g_Sw read happens before its zeroing: same thread)
        if (t == 0 && sel_off >= 1) {
            out[0] = (float)(g_Sw / (g_Sb + 1e-8));
            g_Sw = 0.0;
        }
        for (int i = t; i < KCLS*D; i += blockDim.x) g_sums[i] = 0.f;
        if (t < KCLS) g_counts[t] = 0;
    }
    __syncthreads();
    int sel = 0;
    if (t < TB) {
        const float v = s_v[t];
        const float4* sv4 = (const float4*)s_v;
        int rank = 0;
        #pragma unroll 5
        for (int j4 = 0; j4 < TB/4; j4++) {
            const float4 q = sv4[j4];
            const int jb = j4 * 4;
            rank += (q.x > v) || (q.x == v && jb     < t);
            rank += (q.y > v) || (q.y == v && jb + 1 < t);
            rank += (q.z > v) || (q.z == v && jb + 2 < t);
            rank += (q.w > v) || (q.w == v && jb + 3 < t);
        }
        sel = (rank < TOPK);
    }
    const unsigned bal = __ballot_sync(0xffffffffu, sel);
    if (lane == 0) s_warpcnt[w] = __popc(bal);
    __syncthreads();
    if (sel) {
        int base = 0;
        for (int i = 0; i < w; i++) base += s_warpcnt[i];
        const int pos = base + __popc(bal & ((1u << lane) - 1u));
        g_idx[n*TOPK + pos] = t;
    }
}

// ---------------- kernel 4: flat gather, 4 elements per thread ----------
// Each block owns a 1024-element tile of float2 output elements; thread tid
// handles tile+tid, +256, +512, +768 (coalesced within each group, 4
// independent load chains in flight). Scalar stores (dst 4B-aligned only).
__global__ void __launch_bounds__(256) k_gather(const float2* __restrict__ x,
                                                float* __restrict__ out,
                                                int sel_off) {
    const int TOT2 = NB * CC * TOPK * VV;    // 1,228,800 float2 elems
    const int base = blockIdx.x * 1024 + threadIdx.x;
    int   idx[4];
    float2 val[4];
    #pragma unroll
    for (int k = 0; k < 4; k++) {
        const int i = base + k * 256;
        idx[k] = i;
        if (i < TOT2) {
            const int v   = i % VV;
            const int r1  = i / VV;
            const int j   = r1 & (TOPK - 1);
            const int r2  = r1 >> 6;
            const int c   = r2 % CC;
            const int n   = r2 / CC;
            const int t   = __ldg(&g_idx[n*TOPK + j]);
            val[k] = __ldg(&x[((size_t)(n*CC + c) * TB + t) * VV + v]);
        }
    }
    #pragma unroll
    for (int k = 0; k < 4; k++) {
        if (idx[k] < TOT2) {
            float* op = out + sel_off + 2*(size_t)idx[k];
            op[0] = val[k].x;
            op[1] = val[k].y;
        }
    }
}

extern "C" void kernel_launch(void* const* d_in, const int* in_sizes, int n_in,
                              void* d_out, int out_size) {
    const float2* x   = (const float2*)d_in[0];   // x [256,3,300,25,2]
    const float4* xT  = (const float4*)d_in[1];   // x_T [153600, 256]
    const int*    lab = (const int*)d_in[2];      // labels [153600] int32
    float* out = (float*)d_out;

    const int sel_off = out_size - SEL_ELEMS;     // loss scalar(s) precede x_select

    k_segsum<<<296, 256>>>(xT, lab);
    k_intra<<<592, 256>>>(xT, lab);
    k_topk<<<NB, 320>>>(out, sel_off);
    const int TOT2 = NB * CC * TOPK * VV;
    k_gather<<<(TOT2 + 1023) / 1024, 256>>>(x, out, sel_off);
}